// round 9
// baseline (speedup 1.0000x reference)
#include <cuda_runtime.h>
#include <cstdint>

#define NPAPER 100000
#define NAUTH  50000
#define NINST  5000
#define NTOT   155000
#define SRCROWS 305000
#define ETOT   900000

// ---------------- device scratch (no allocations allowed) ----------------
__device__ __align__(256) float g_X[(size_t)NTOT*128];
__device__ __align__(256) float g_Y[(size_t)NTOT*128];
__device__ __align__(256) float g_KQV[(size_t)NTOT*384];
__device__ __align__(256) float g_KR[(size_t)SRCROWS*128];
__device__ __align__(256) float g_VR[(size_t)SRCROWS*128];
__device__ __align__(256) float g_DEN[(size_t)NTOT*8];
__device__ __align__(256) float g_AGG[(size_t)NTOT*128];
__device__ int g_flags[3];

// ---------------- helpers ----------------

__device__ __forceinline__ float gelu_f(float x) {
    return 0.5f * x * (1.f + erff(x * 0.70710678118654752f));
}

__device__ __forceinline__ void split_tf32(float v, float& hi, float& lo) {
    uint32_t h, l;
    asm("cvt.rna.tf32.f32 %0, %1;" : "=r"(h) : "f"(v));
    float hf = __uint_as_float(h);
    asm("cvt.rna.tf32.f32 %0, %1;" : "=r"(l) : "f"(v - hf));
    hi = hf; lo = __uint_as_float(l);
}

__device__ __forceinline__ void mma_tf32(float c[4], const uint32_t a[4],
                                         uint32_t b0, uint32_t b1) {
    asm volatile(
        "mma.sync.aligned.m16n8k8.row.col.f32.tf32.tf32.f32 "
        "{%0,%1,%2,%3}, {%4,%5,%6,%7}, {%8,%9}, {%0,%1,%2,%3};"
        : "+f"(c[0]), "+f"(c[1]), "+f"(c[2]), "+f"(c[3])
        : "r"(a[0]), "r"(a[1]), "r"(a[2]), "r"(a[3]), "r"(b0), "r"(b1));
}

__device__ __forceinline__ void red_add_v4(float* p, float4 v) {
    asm volatile("red.global.add.v4.f32 [%0], {%1,%2,%3,%4};"
        :: "l"(p), "f"(v.x), "f"(v.y), "f"(v.z), "f"(v.w) : "memory");
}

__device__ __forceinline__ void red_add_f(float* p, float v) {
    asm volatile("red.global.add.f32 [%0], %1;" :: "l"(p), "f"(v) : "memory");
}

__device__ __forceinline__ int edge_src(const int* b, int e, int E, int lay) {
    return lay ? b[2 * e] : b[e];
}
__device__ __forceinline__ int edge_dst(const int* b, int e, int E, int lay) {
    return lay ? b[2 * e + 1] : b[E + e];
}

struct GB {  // per-node-type batched GEMM descriptors (z-indexed)
    const float* A[3];
    const float* W[3];
    const float* Bias[3];
    float*       C[3];
    const float* R[3];
    const float* S[3];
    const float* D[3];   // per-row/head denominators (A pre-divide), or null
    int M[3], K[3], lda[3], ldw[3], ldc[3];
    int H;               // heads for D indexing
};

// ---------------- kernels ----------------

__global__ void resolve_kernel(const int* __restrict__ t01,
                               const int* __restrict__ t34a,
                               const int* __restrict__ t34b)
{
    __shared__ int s[8];
    if (threadIdx.x < 8) s[threadIdx.x] = 0;
    __syncthreads();
    int ah1 = 0, ah2 = 0, aodd = 0, bh1 = 0, bh2 = 0, bodd = 0, ch1 = 0, cev = 0;
    for (int i = threadIdx.x; i < 200000; i += blockDim.x) {
        int va = t34a[i], vb = t34b[i];
        if (i < 100000) { ah1 = max(ah1, va); bh1 = max(bh1, vb); }
        else            { ah2 = max(ah2, va); bh2 = max(bh2, vb); }
        if (i & 1) { aodd = max(aodd, va); bodd = max(bodd, vb); }
    }
    for (int i = threadIdx.x; i < 500000; i += blockDim.x) {
        int vc = t01[i];
        if (i < 250000) ch1 = max(ch1, vc);
        if (!(i & 1))   cev = max(cev, vc);
    }
    atomicMax(&s[0], ah1); atomicMax(&s[1], ah2); atomicMax(&s[2], aodd);
    atomicMax(&s[3], bh1); atomicMax(&s[4], bh2); atomicMax(&s[5], bodd);
    atomicMax(&s[6], ch1); atomicMax(&s[7], cev);
    __syncthreads();
    if (threadIdx.x == 0) {
        int m4 = min(min(s[0], s[1]), min(s[3], s[4]));
        int layE2 = (m4 >= 10000) ? 1 : 0;
        g_flags[2] = layE2;
        g_flags[1] = layE2 ? ((s[2] >= 10000) ? 1 : 0)
                           : ((s[1] >= 10000) ? 1 : 0);
        int srcmax = layE2 ? s[7] : s[6];
        g_flags[0] = (srcmax >= 60000) ? 1 : 0;
    }
}

__global__ void init_kernel(float4* __restrict__ D, float4* __restrict__ A,
                            int nD4, int nA4) {
    int i = blockIdx.x * blockDim.x + threadIdx.x;
    float4 z = make_float4(0.f, 0.f, 0.f, 0.f);
    if (i < nD4) D[i] = z;
    if (i < nA4) A[i] = z;
}

// Batched (z = node type) C = epilogue(actA(A) @ W + bias) via 3xTF32 MMA.
// Block tile 128x64x32 with register-prefetch pipeline. K % 32 == 0.
// If D[z] != null, A element (m, k) is pre-divided by D[m*H + k/16] (softmax
// normalization folded into the load), before optional gelu.
__global__ __launch_bounds__(256)
void gemm_tf32(GB gb, int geluA, int reluO)
{
    const int z = blockIdx.z;
    const int M = gb.M[z];
    const int m0 = blockIdx.y * 128;
    if (m0 >= M) return;
    const int K = gb.K[z], lda = gb.lda[z], ldw = gb.ldw[z], ldc = gb.ldc[z];
    const float* __restrict__ A = gb.A[z];
    const float* __restrict__ W = gb.W[z];
    const float* __restrict__ bias = gb.Bias[z];
    const float* __restrict__ resid = gb.R[z];
    const float* __restrict__ Dn = gb.D[z];
    const int H = gb.H;
    float* __restrict__ C = gb.C[z];

    __shared__ float Ah[32][129], Al[32][129];   // [k][m]
    __shared__ float Bh[64][33],  Bl[64][33];    // [n][k]
    const int tid = threadIdx.x;
    const int lane = tid & 31, wid = tid >> 5;
    const int n0 = blockIdx.x * 64;
    const int moff = (wid & 3) * 32, noff = (wid >> 2) * 32;
    const int am = tid & 127, ak = (tid >> 7) * 16;
    const int bk = tid & 31,  bn = (tid >> 5) * 8;
    const bool arow_ok = (m0 + am < M);

    float c[2][4][4];
#pragma unroll
    for (int mt = 0; mt < 2; mt++)
#pragma unroll
        for (int nt = 0; nt < 4; nt++)
#pragma unroll
            for (int i = 0; i < 4; i++) c[mt][nt][i] = 0.f;

    float4 ra[4], rb[2];
    const float4 fz = make_float4(0.f, 0.f, 0.f, 0.f);

#define LDG_TILE(K0)                                                          \
    do {                                                                      \
        const float* ap = A + (size_t)(m0 + am) * lda + (K0) + ak;            \
        if (arow_ok) {                                                        \
            ra[0] = *(const float4*)(ap);      ra[1] = *(const float4*)(ap + 4); \
            ra[2] = *(const float4*)(ap + 8);  ra[3] = *(const float4*)(ap + 12);\
        } else { ra[0] = fz; ra[1] = fz; ra[2] = fz; ra[3] = fz; }             \
        if (Dn && arow_ok) {                                                  \
            float dn = __ldg(Dn + (size_t)(m0 + am) * H + (((K0) + ak) >> 4)); \
            float inv = 1.f / fmaxf(dn, 1e-16f);                              \
            _Pragma("unroll")                                                 \
            for (int j = 0; j < 4; j++) {                                     \
                ra[j].x *= inv; ra[j].y *= inv; ra[j].z *= inv; ra[j].w *= inv; \
            }                                                                 \
        }                                                                     \
        if (geluA) {                                                          \
            _Pragma("unroll")                                                 \
            for (int j = 0; j < 4; j++) {                                     \
                ra[j].x = gelu_f(ra[j].x); ra[j].y = gelu_f(ra[j].y);         \
                ra[j].z = gelu_f(ra[j].z); ra[j].w = gelu_f(ra[j].w);         \
            }                                                                 \
        }                                                                     \
        const float* bp = W + (size_t)((K0) + bk) * ldw + n0 + bn;            \
        rb[0] = *(const float4*)(bp); rb[1] = *(const float4*)(bp + 4);       \
    } while (0)

    LDG_TILE(0);
    const int niter = K >> 5;
    for (int it = 0; it < niter; it++) {
        __syncthreads();
#pragma unroll
        for (int j = 0; j < 4; j++) {
            float h, l;
            split_tf32(ra[j].x, h, l); Ah[ak + j*4 + 0][am] = h; Al[ak + j*4 + 0][am] = l;
            split_tf32(ra[j].y, h, l); Ah[ak + j*4 + 1][am] = h; Al[ak + j*4 + 1][am] = l;
            split_tf32(ra[j].z, h, l); Ah[ak + j*4 + 2][am] = h; Al[ak + j*4 + 2][am] = l;
            split_tf32(ra[j].w, h, l); Ah[ak + j*4 + 3][am] = h; Al[ak + j*4 + 3][am] = l;
        }
#pragma unroll
        for (int j = 0; j < 2; j++) {
            float h, l;
            split_tf32(rb[j].x, h, l); Bh[bn + j*4 + 0][bk] = h; Bl[bn + j*4 + 0][bk] = l;
            split_tf32(rb[j].y, h, l); Bh[bn + j*4 + 1][bk] = h; Bl[bn + j*4 + 1][bk] = l;
            split_tf32(rb[j].z, h, l); Bh[bn + j*4 + 2][bk] = h; Bl[bn + j*4 + 2][bk] = l;
            split_tf32(rb[j].w, h, l); Bh[bn + j*4 + 3][bk] = h; Bl[bn + j*4 + 3][bk] = l;
        }
        __syncthreads();
        if (it + 1 < niter) LDG_TILE((it + 1) << 5);
#pragma unroll
        for (int ks = 0; ks < 32; ks += 8) {
            const int kk = ks + (lane & 3);
            uint32_t ah[2][4], al[2][4];
#pragma unroll
            for (int mt = 0; mt < 2; mt++) {
                int r = moff + mt * 16 + (lane >> 2);
                ah[mt][0] = __float_as_uint(Ah[kk][r]);
                ah[mt][1] = __float_as_uint(Ah[kk][r + 8]);
                ah[mt][2] = __float_as_uint(Ah[kk + 4][r]);
                ah[mt][3] = __float_as_uint(Ah[kk + 4][r + 8]);
                al[mt][0] = __float_as_uint(Al[kk][r]);
                al[mt][1] = __float_as_uint(Al[kk][r + 8]);
                al[mt][2] = __float_as_uint(Al[kk + 4][r]);
                al[mt][3] = __float_as_uint(Al[kk + 4][r + 8]);
            }
#pragma unroll
            for (int nt = 0; nt < 4; nt++) {
                int bc = noff + nt * 8 + (lane >> 2);
                uint32_t bh0 = __float_as_uint(Bh[bc][kk]);
                uint32_t bh1 = __float_as_uint(Bh[bc][kk + 4]);
                uint32_t bl0 = __float_as_uint(Bl[bc][kk]);
                uint32_t bl1 = __float_as_uint(Bl[bc][kk + 4]);
#pragma unroll
                for (int mt = 0; mt < 2; mt++) {
                    mma_tf32(c[mt][nt], al[mt], bh0, bh1);
                    mma_tf32(c[mt][nt], ah[mt], bl0, bl1);
                    mma_tf32(c[mt][nt], ah[mt], bh0, bh1);
                }
            }
        }
    }
#undef LDG_TILE

    float sa = 0.f;
    if (resid) { float s = *gb.S[z]; sa = 1.f / (1.f + __expf(-s)); }
#pragma unroll
    for (int mt = 0; mt < 2; mt++) {
#pragma unroll
        for (int half = 0; half < 2; half++) {
            int cm = m0 + moff + mt * 16 + (lane >> 2) + half * 8;
            if (cm >= M) continue;
#pragma unroll
            for (int nt = 0; nt < 4; nt++) {
                int cn = n0 + noff + nt * 8 + (lane & 3) * 2;
                float v0 = c[mt][nt][half * 2 + 0] + bias[cn];
                float v1 = c[mt][nt][half * 2 + 1] + bias[cn + 1];
                if (reluO) { v0 = fmaxf(v0, 0.f); v1 = fmaxf(v1, 0.f); }
                if (resid) {
                    float2 r2 = *(const float2*)(resid + (size_t)cm * ldc + cn);
                    v0 = sa * v0 + (1.f - sa) * r2.x;
                    v1 = sa * v1 + (1.f - sa) * r2.y;
                }
                *(float2*)(C + (size_t)cm * ldc + cn) = make_float2(v0, v1);
            }
        }
    }
}

// Per-edge-type relation transform over source nodes, reading fused KQV.
__global__ __launch_bounds__(256)
void relx_kernel(const float* __restrict__ KQV, int S, int foutp,
                 const float* __restrict__ krel, const float* __restrict__ vrel,
                 float* __restrict__ KR, float* __restrict__ VR, int nsrc, int H)
{
    extern __shared__ float sh[];
    float* skr = sh;
    float* svr = sh + H * 256;
    for (int i = threadIdx.x; i < H * 256; i += blockDim.x) {
        skr[i] = krel[i]; svr[i] = vrel[i];
    }
    __syncthreads();
    const int fout = H << 4;
    int tid = blockIdx.x * blockDim.x + threadIdx.x;
    if (tid >= nsrc * fout) return;
    int n = tid / fout, c = tid - n * fout;
    int h = c >> 4, eo = c & 15;
    const float4* kin = (const float4*)(KQV + (size_t)n * S + h * 16);
    const float4* vin = (const float4*)(KQV + (size_t)n * S + 2 * foutp + h * 16);
    const float* km = skr + h * 256 + eo;
    const float* vm = svr + h * 256 + eo;
    float ak = 0.f, av = 0.f;
#pragma unroll
    for (int j = 0; j < 4; j++) {
        float4 k4 = kin[j], v4 = vin[j];
        const float* kmj = km + (j << 6);
        const float* vmj = vm + (j << 6);
        ak += k4.x * kmj[0] + k4.y * kmj[16] + k4.z * kmj[32] + k4.w * kmj[48];
        av += v4.x * vmj[0] + v4.y * vmj[16] + v4.z * vmj[32] + v4.w * vmj[48];
    }
    KR[tid] = ak; VR[tid] = av;
}

// ONE-PASS edge kernel: score -> exp -> accumulate unnormalized message and
// denominator.  Normalization by den happens in the out-projection GEMM.
__global__ __launch_bounds__(256)
void edge_kernel(const int* __restrict__ ep0, const int* __restrict__ ep1,
                 const int* __restrict__ flagp, const int* __restrict__ layp,
                 const float* __restrict__ Qb, int S,
                 const float* __restrict__ KR, const float* __restrict__ VR,
                 const float* __restrict__ prel,
                 float* __restrict__ Db, float* __restrict__ AG,
                 int E, int H, int ns, int nd)
{
    const int* base = (*flagp) ? ep1 : ep0;
    const int lay = *layp;
    int tid = blockIdx.x * blockDim.x + threadIdx.x;
    if (tid >= E * H) return;
    int e = tid / H, h = tid - e * H;
    int s = min(max(edge_src(base, e, E, lay), 0), ns - 1);
    int d = min(max(edge_dst(base, e, E, lay), 0), nd - 1);
    const float4* q = (const float4*)(Qb + (size_t)d * S + h * 16);
    const float4* k = (const float4*)(KR + ((size_t)s * H + h) * 16);
    float sc = 0.f;
#pragma unroll
    for (int j = 0; j < 4; j++) {
        float4 qa = q[j], kb = k[j];
        sc += qa.x * kb.x + qa.y * kb.y + qa.z * kb.z + qa.w * kb.w;
    }
    sc *= prel[h] * 0.25f;
    float ex = __expf(sc);
    red_add_f(Db + (size_t)d * H + h, ex);
    const float4* v = (const float4*)(VR + ((size_t)s * H + h) * 16);
    float* ap = AG + ((size_t)d * H + h) * 16;
#pragma unroll
    for (int j = 0; j < 4; j++) {
        float4 vv = v[j];
        vv.x *= ex; vv.y *= ex; vv.z *= ex; vv.w *= ex;
        red_add_v4(ap + j * 4, vv);
    }
}

// ---------------- host orchestration ----------------

extern "C" void kernel_launch(void* const* d_in, const int* in_sizes, int n_in,
                              void* d_out, int out_size)
{
    static const long long ESIZE[30] = {
        25600000, 6400000, 320000,
        500000, 500000, 400000, 200000, 200000,
        32768, 128, 16384, 128, 8192, 128,
        147456, 1152, 10240, 10240, 40, 49152, 384, 3,
        73728, 576, 5120, 5120, 20, 12288, 192, 3
    };
    const void* P[30];
    bool got[30];
    for (int j = 0; j < 30; j++) { got[j] = false; P[j] = nullptr; }
    for (int i = 0; i < n_in; i++) {
        for (int j = 0; j < 30; j++) {
            if (!got[j] && (long long)in_sizes[i] == ESIZE[j]) {
                P[j] = d_in[i]; got[j] = true; break;
            }
        }
    }
    for (int j = 0; j < 30; j++) if (!got[j]) return;

    const float* x_in[3]  = {(const float*)P[0], (const float*)P[1], (const float*)P[2]};
    const int*   eptr[5]  = {(const int*)P[3], (const int*)P[4], (const int*)P[5],
                             (const int*)P[6], (const int*)P[7]};
    const float* lin_w[3] = {(const float*)P[8], (const float*)P[10], (const float*)P[12]};
    const float* lin_b[3] = {(const float*)P[9], (const float*)P[11], (const float*)P[13]};
    const float* kqv_w[2] = {(const float*)P[14], (const float*)P[22]};
    const float* kqv_b[2] = {(const float*)P[15], (const float*)P[23]};
    const float* krel[2]  = {(const float*)P[16], (const float*)P[24]};
    const float* vrel[2]  = {(const float*)P[17], (const float*)P[25]};
    const float* prel[2]  = {(const float*)P[18], (const float*)P[26]};
    const float* outw[2]  = {(const float*)P[19], (const float*)P[27]};
    const float* outb[2]  = {(const float*)P[20], (const float*)P[28]};
    const float* skipv[2] = {(const float*)P[21], (const float*)P[29]};

    float *X, *Y, *KQV, *KR, *VR, *Db, *AG;
    int* FL;
#define GETSYM(p, s) do { if (cudaGetSymbolAddress((void**)&(p), s) != cudaSuccess) return; } while (0)
    GETSYM(X,  g_X);  GETSYM(Y,  g_Y);  GETSYM(KQV, g_KQV);
    GETSYM(KR, g_KR); GETSYM(VR, g_VR);
    GETSYM(Db, g_DEN); GETSYM(AG, g_AGG); GETSYM(FL, g_flags);
#undef GETSYM

    const int ntyp[3]  = {NPAPER, NAUTH, NINST};
    const int roff[3]  = {0, NPAPER, NPAPER + NAUTH};
    const int idim[3]  = {256, 128, 64};
    // EDGE_TYPES = [(1,0), (0,0), (0,1), (1,2), (2,1)]
    const int esrc[5]  = {1, 0, 0, 1, 2};
    const int edst[5]  = {0, 0, 1, 2, 1};
    const int ecnt[5]  = {250000, 250000, 200000, 100000, 100000};
    const int kroff[5] = {0, 50000, 150000, 250000, 300000};
    const int* epri[5]  = {eptr[0], eptr[1], eptr[2], eptr[3], eptr[4]};
    const int* ealt[5]  = {eptr[1], eptr[0], eptr[2], eptr[4], eptr[3]};
    const int* eflag[5] = {FL + 0, FL + 0, FL + 0, FL + 1, FL + 1};
    int* LAY = FL + 2;

    resolve_kernel<<<1, 1024>>>(eptr[0], eptr[3], eptr[4]);

    const int MAXMB = (NPAPER + 127) / 128;   // 782

    // ---- input projections: X = relu(x @ lin_w + lin_b) ----
    {
        GB gb; gb.H = 1;
        for (int t = 0; t < 3; t++) {
            gb.A[t] = x_in[t];  gb.lda[t] = idim[t];
            gb.W[t] = lin_w[t]; gb.ldw[t] = 128;
            gb.Bias[t] = lin_b[t];
            gb.C[t] = X + (size_t)roff[t] * 128; gb.ldc[t] = 128;
            gb.R[t] = nullptr; gb.S[t] = nullptr; gb.D[t] = nullptr;
            gb.M[t] = ntyp[t]; gb.K[t] = idim[t];
        }
        gemm_tf32<<<dim3(2, MAXMB, 3), 256>>>(gb, 0, 1);
    }

    for (int li = 0; li < 2; li++) {
        const int H = li ? 4 : 8;
        const int fout = H * 16;
        const int S = 3 * fout;
        const float* Xin = li ? Y : X;

        // fused kqv projection, batched over types
        {
            GB gb; gb.H = 1;
            for (int t = 0; t < 3; t++) {
                gb.A[t] = Xin + (size_t)roff[t] * 128; gb.lda[t] = 128;
                gb.W[t] = kqv_w[li] + (size_t)t * 128 * S; gb.ldw[t] = S;
                gb.Bias[t] = kqv_b[li] + t * S;
                gb.C[t] = KQV + (size_t)roff[t] * S; gb.ldc[t] = S;
                gb.R[t] = nullptr; gb.S[t] = nullptr; gb.D[t] = nullptr;
                gb.M[t] = ntyp[t]; gb.K[t] = 128;
            }
            gemm_tf32<<<dim3(S / 64, MAXMB, 3), 256>>>(gb, 0, 0);
        }

        // init segment buffers (den + agg)
        {
            int nD4 = NTOT * H / 4, nA4 = NTOT * fout / 4;
            init_kernel<<<(nA4 + 255) / 256, 256>>>((float4*)Db, (float4*)AG, nD4, nA4);
        }

        // per-edge-type relation transforms over source nodes
        for (int e = 0; e < 5; e++) {
            int ns = ntyp[esrc[e]];
            int tot = ns * fout;
            size_t shb = (size_t)2 * H * 256 * sizeof(float);
            relx_kernel<<<(tot + 255) / 256, 256, shb>>>(
                KQV + (size_t)roff[esrc[e]] * S, S, fout,
                krel[li] + e * H * 256, vrel[li] + e * H * 256,
                KR + (size_t)kroff[e] * fout, VR + (size_t)kroff[e] * fout, ns, H);
        }

        // ONE-PASS edge phase: score + exp + unnormalized aggregation
        for (int e = 0; e < 5; e++) {
            int tot = ecnt[e] * H;
            edge_kernel<<<(tot + 255) / 256, 256>>>(
                epri[e], ealt[e], eflag[e], LAY,
                KQV + (size_t)roff[edst[e]] * S + fout, S,
                KR + (size_t)kroff[e] * fout, VR + (size_t)kroff[e] * fout,
                prel[li] + e * H,
                Db + (size_t)roff[edst[e]] * H,
                AG + (size_t)roff[edst[e]] * fout,
                ecnt[e], H, ntyp[esrc[e]], ntyp[edst[e]]);
        }

        // output projection (batched; normalizes A by den inside the load)
        if (li == 0) {
            GB gb; gb.H = H;
            for (int t = 0; t < 3; t++) {
                gb.A[t] = AG + (size_t)roff[t] * 128; gb.lda[t] = 128;
                gb.W[t] = outw[0] + (size_t)t * 128 * 128; gb.ldw[t] = 128;
                gb.Bias[t] = outb[0] + t * 128;
                gb.C[t] = Y + (size_t)roff[t] * 128; gb.ldc[t] = 128;
                gb.R[t] = Xin + (size_t)roff[t] * 128; gb.S[t] = skipv[0] + t;
                gb.D[t] = Db + (size_t)roff[t] * H;
                gb.M[t] = ntyp[t]; gb.K[t] = 128;
            }
            gemm_tf32<<<dim3(2, MAXMB, 3), 256>>>(gb, 1, 0);
        } else {
            const size_t ooff[3] = {0, (size_t)NPAPER * 64, (size_t)(NPAPER + NAUTH) * 64};
            const long long need[3] = {6400000LL, 9600000LL, 9920000LL};
            GB gb; gb.H = H;
            for (int t = 0; t < 3; t++) {
                gb.A[t] = AG + (size_t)roff[t] * 64; gb.lda[t] = 64;
                gb.W[t] = outw[1] + (size_t)t * 64 * 64; gb.ldw[t] = 64;
                gb.Bias[t] = outb[1] + t * 64;
                gb.C[t] = (float*)d_out + ooff[t]; gb.ldc[t] = 64;
                gb.R[t] = nullptr; gb.S[t] = nullptr;
                gb.D[t] = Db + (size_t)roff[t] * H;
                gb.M[t] = ((long long)out_size >= need[t]) ? ntyp[t] : 0;
                gb.K[t] = 64;
            }
            gemm_tf32<<<dim3(1, MAXMB, 3), 256>>>(gb, 1, 0);
        }
    }
}

// round 10
// speedup vs baseline: 1.5129x; 1.5129x over previous
#include <cuda_runtime.h>
#include <cstdint>

#define NPAPER 100000
#define NAUTH  50000
#define NINST  5000
#define NTOT   155000
#define SRCROWS 305000
#define ETOT   900000

// ---------------- device scratch (no allocations allowed) ----------------
__device__ __align__(256) float g_X[(size_t)NTOT*128];
__device__ __align__(256) float g_Y[(size_t)NTOT*128];
__device__ __align__(256) float g_KQV[(size_t)NTOT*384];
__device__ __align__(256) float g_KR[(size_t)SRCROWS*128];
__device__ __align__(256) float g_VR[(size_t)SRCROWS*128];
__device__ __align__(256) float g_SC[(size_t)ETOT*8];
__device__ __align__(256) float g_DEN[(size_t)NTOT*8];
__device__ __align__(256) float g_AGG[(size_t)NTOT*128];
__device__ int g_flags[3];

// ---------------- helpers ----------------

__device__ __forceinline__ float gelu_f(float x) {
    return 0.5f * x * (1.f + erff(x * 0.70710678118654752f));
}

__device__ __forceinline__ void split_tf32(float v, float& hi, float& lo) {
    uint32_t h, l;
    asm("cvt.rna.tf32.f32 %0, %1;" : "=r"(h) : "f"(v));
    float hf = __uint_as_float(h);
    asm("cvt.rna.tf32.f32 %0, %1;" : "=r"(l) : "f"(v - hf));
    hi = hf; lo = __uint_as_float(l);
}

__device__ __forceinline__ void mma_tf32(float c[4], const uint32_t a[4],
                                         uint32_t b0, uint32_t b1) {
    asm volatile(
        "mma.sync.aligned.m16n8k8.row.col.f32.tf32.tf32.f32 "
        "{%0,%1,%2,%3}, {%4,%5,%6,%7}, {%8,%9}, {%0,%1,%2,%3};"
        : "+f"(c[0]), "+f"(c[1]), "+f"(c[2]), "+f"(c[3])
        : "r"(a[0]), "r"(a[1]), "r"(a[2]), "r"(a[3]), "r"(b0), "r"(b1));
}

__device__ __forceinline__ void red_add_v4(float* p, float4 v) {
    asm volatile("red.global.add.v4.f32 [%0], {%1,%2,%3,%4};"
        :: "l"(p), "f"(v.x), "f"(v.y), "f"(v.z), "f"(v.w) : "memory");
}

__device__ __forceinline__ int edge_src(const int* b, int e, int E, int lay) {
    return lay ? b[2 * e] : b[e];
}
__device__ __forceinline__ int edge_dst(const int* b, int e, int E, int lay) {
    return lay ? b[2 * e + 1] : b[E + e];
}

struct GB {  // per-node-type batched GEMM descriptors (z-indexed)
    const float* A[3];
    const float* W[3];
    const float* Bias[3];
    float*       C[3];
    const float* R[3];
    const float* S[3];
    const float* D[3];   // per-row/head denominators (A pre-divide), or null
    int M[3], K[3], lda[3], ldw[3], ldc[3];
    int H;               // heads for D indexing
};

// ---------------- kernels ----------------

__global__ void resolve_kernel(const int* __restrict__ t01,
                               const int* __restrict__ t34a,
                               const int* __restrict__ t34b)
{
    __shared__ int s[8];
    if (threadIdx.x < 8) s[threadIdx.x] = 0;
    __syncthreads();
    int ah1 = 0, ah2 = 0, aodd = 0, bh1 = 0, bh2 = 0, bodd = 0, ch1 = 0, cev = 0;
    for (int i = threadIdx.x; i < 200000; i += blockDim.x) {
        int va = t34a[i], vb = t34b[i];
        if (i < 100000) { ah1 = max(ah1, va); bh1 = max(bh1, vb); }
        else            { ah2 = max(ah2, va); bh2 = max(bh2, vb); }
        if (i & 1) { aodd = max(aodd, va); bodd = max(bodd, vb); }
    }
    for (int i = threadIdx.x; i < 500000; i += blockDim.x) {
        int vc = t01[i];
        if (i < 250000) ch1 = max(ch1, vc);
        if (!(i & 1))   cev = max(cev, vc);
    }
    atomicMax(&s[0], ah1); atomicMax(&s[1], ah2); atomicMax(&s[2], aodd);
    atomicMax(&s[3], bh1); atomicMax(&s[4], bh2); atomicMax(&s[5], bodd);
    atomicMax(&s[6], ch1); atomicMax(&s[7], cev);
    __syncthreads();
    if (threadIdx.x == 0) {
        int m4 = min(min(s[0], s[1]), min(s[3], s[4]));
        int layE2 = (m4 >= 10000) ? 1 : 0;
        g_flags[2] = layE2;
        g_flags[1] = layE2 ? ((s[2] >= 10000) ? 1 : 0)
                           : ((s[1] >= 10000) ? 1 : 0);
        int srcmax = layE2 ? s[7] : s[6];
        g_flags[0] = (srcmax >= 60000) ? 1 : 0;
    }
}

__global__ void init_kernel(float4* __restrict__ D, float4* __restrict__ A,
                            int nD4, int nA4) {
    int i = blockIdx.x * blockDim.x + threadIdx.x;
    float4 z = make_float4(0.f, 0.f, 0.f, 0.f);
    if (i < nD4) D[i] = z;
    if (i < nA4) A[i] = z;
}

// Batched (z = node type) C = epilogue(actA(A) @ W + bias) via 3xTF32 MMA.
// Block tile 128x64x32 with register-prefetch pipeline. K % 32 == 0.
// If D[z] != null, A element (m, k) is pre-divided by D[m*H + k/16].
__global__ __launch_bounds__(256)
void gemm_tf32(GB gb, int geluA, int reluO)
{
    const int z = blockIdx.z;
    const int M = gb.M[z];
    const int m0 = blockIdx.y * 128;
    if (m0 >= M) return;
    const int K = gb.K[z], lda = gb.lda[z], ldw = gb.ldw[z], ldc = gb.ldc[z];
    const float* __restrict__ A = gb.A[z];
    const float* __restrict__ W = gb.W[z];
    const float* __restrict__ bias = gb.Bias[z];
    const float* __restrict__ resid = gb.R[z];
    const float* __restrict__ Dn = gb.D[z];
    const int H = gb.H;
    float* __restrict__ C = gb.C[z];

    __shared__ float Ah[32][129], Al[32][129];   // [k][m]
    __shared__ float Bh[64][33],  Bl[64][33];    // [n][k]
    const int tid = threadIdx.x;
    const int lane = tid & 31, wid = tid >> 5;
    const int n0 = blockIdx.x * 64;
    const int moff = (wid & 3) * 32, noff = (wid >> 2) * 32;
    const int am = tid & 127, ak = (tid >> 7) * 16;
    const int bk = tid & 31,  bn = (tid >> 5) * 8;
    const bool arow_ok = (m0 + am < M);

    float c[2][4][4];
#pragma unroll
    for (int mt = 0; mt < 2; mt++)
#pragma unroll
        for (int nt = 0; nt < 4; nt++)
#pragma unroll
            for (int i = 0; i < 4; i++) c[mt][nt][i] = 0.f;

    float4 ra[4], rb[2];
    const float4 fz = make_float4(0.f, 0.f, 0.f, 0.f);

#define LDG_TILE(K0)                                                          \
    do {                                                                      \
        const float* ap = A + (size_t)(m0 + am) * lda + (K0) + ak;            \
        if (arow_ok) {                                                        \
            ra[0] = *(const float4*)(ap);      ra[1] = *(const float4*)(ap + 4); \
            ra[2] = *(const float4*)(ap + 8);  ra[3] = *(const float4*)(ap + 12);\
        } else { ra[0] = fz; ra[1] = fz; ra[2] = fz; ra[3] = fz; }             \
        if (Dn && arow_ok) {                                                  \
            float dn = __ldg(Dn + (size_t)(m0 + am) * H + (((K0) + ak) >> 4)); \
            float inv = 1.f / fmaxf(dn, 1e-16f);                              \
            _Pragma("unroll")                                                 \
            for (int j = 0; j < 4; j++) {                                     \
                ra[j].x *= inv; ra[j].y *= inv; ra[j].z *= inv; ra[j].w *= inv; \
            }                                                                 \
        }                                                                     \
        if (geluA) {                                                          \
            _Pragma("unroll")                                                 \
            for (int j = 0; j < 4; j++) {                                     \
                ra[j].x = gelu_f(ra[j].x); ra[j].y = gelu_f(ra[j].y);         \
                ra[j].z = gelu_f(ra[j].z); ra[j].w = gelu_f(ra[j].w);         \
            }                                                                 \
        }                                                                     \
        const float* bp = W + (size_t)((K0) + bk) * ldw + n0 + bn;            \
        rb[0] = *(const float4*)(bp); rb[1] = *(const float4*)(bp + 4);       \
    } while (0)

    LDG_TILE(0);
    const int niter = K >> 5;
    for (int it = 0; it < niter; it++) {
        __syncthreads();
#pragma unroll
        for (int j = 0; j < 4; j++) {
            float h, l;
            split_tf32(ra[j].x, h, l); Ah[ak + j*4 + 0][am] = h; Al[ak + j*4 + 0][am] = l;
            split_tf32(ra[j].y, h, l); Ah[ak + j*4 + 1][am] = h; Al[ak + j*4 + 1][am] = l;
            split_tf32(ra[j].z, h, l); Ah[ak + j*4 + 2][am] = h; Al[ak + j*4 + 2][am] = l;
            split_tf32(ra[j].w, h, l); Ah[ak + j*4 + 3][am] = h; Al[ak + j*4 + 3][am] = l;
        }
#pragma unroll
        for (int j = 0; j < 2; j++) {
            float h, l;
            split_tf32(rb[j].x, h, l); Bh[bn + j*4 + 0][bk] = h; Bl[bn + j*4 + 0][bk] = l;
            split_tf32(rb[j].y, h, l); Bh[bn + j*4 + 1][bk] = h; Bl[bn + j*4 + 1][bk] = l;
            split_tf32(rb[j].z, h, l); Bh[bn + j*4 + 2][bk] = h; Bl[bn + j*4 + 2][bk] = l;
            split_tf32(rb[j].w, h, l); Bh[bn + j*4 + 3][bk] = h; Bl[bn + j*4 + 3][bk] = l;
        }
        __syncthreads();
        if (it + 1 < niter) LDG_TILE((it + 1) << 5);
#pragma unroll
        for (int ks = 0; ks < 32; ks += 8) {
            const int kk = ks + (lane & 3);
            uint32_t ah[2][4], al[2][4];
#pragma unroll
            for (int mt = 0; mt < 2; mt++) {
                int r = moff + mt * 16 + (lane >> 2);
                ah[mt][0] = __float_as_uint(Ah[kk][r]);
                ah[mt][1] = __float_as_uint(Ah[kk][r + 8]);
                ah[mt][2] = __float_as_uint(Ah[kk + 4][r]);
                ah[mt][3] = __float_as_uint(Ah[kk + 4][r + 8]);
                al[mt][0] = __float_as_uint(Al[kk][r]);
                al[mt][1] = __float_as_uint(Al[kk][r + 8]);
                al[mt][2] = __float_as_uint(Al[kk + 4][r]);
                al[mt][3] = __float_as_uint(Al[kk + 4][r + 8]);
            }
#pragma unroll
            for (int nt = 0; nt < 4; nt++) {
                int bc = noff + nt * 8 + (lane >> 2);
                uint32_t bh0 = __float_as_uint(Bh[bc][kk]);
                uint32_t bh1 = __float_as_uint(Bh[bc][kk + 4]);
                uint32_t bl0 = __float_as_uint(Bl[bc][kk]);
                uint32_t bl1 = __float_as_uint(Bl[bc][kk + 4]);
#pragma unroll
                for (int mt = 0; mt < 2; mt++) {
                    mma_tf32(c[mt][nt], al[mt], bh0, bh1);
                    mma_tf32(c[mt][nt], ah[mt], bl0, bl1);
                    mma_tf32(c[mt][nt], ah[mt], bh0, bh1);
                }
            }
        }
    }
#undef LDG_TILE

    float sa = 0.f;
    if (resid) { float s = *gb.S[z]; sa = 1.f / (1.f + __expf(-s)); }
#pragma unroll
    for (int mt = 0; mt < 2; mt++) {
#pragma unroll
        for (int half = 0; half < 2; half++) {
            int cm = m0 + moff + mt * 16 + (lane >> 2) + half * 8;
            if (cm >= M) continue;
#pragma unroll
            for (int nt = 0; nt < 4; nt++) {
                int cn = n0 + noff + nt * 8 + (lane & 3) * 2;
                float v0 = c[mt][nt][half * 2 + 0] + bias[cn];
                float v1 = c[mt][nt][half * 2 + 1] + bias[cn + 1];
                if (reluO) { v0 = fmaxf(v0, 0.f); v1 = fmaxf(v1, 0.f); }
                if (resid) {
                    float2 r2 = *(const float2*)(resid + (size_t)cm * ldc + cn);
                    v0 = sa * v0 + (1.f - sa) * r2.x;
                    v1 = sa * v1 + (1.f - sa) * r2.y;
                }
                *(float2*)(C + (size_t)cm * ldc + cn) = make_float2(v0, v1);
            }
        }
    }
}

// Per-edge-type relation transform over source nodes, reading fused KQV.
__global__ __launch_bounds__(256)
void relx_kernel(const float* __restrict__ KQV, int S, int foutp,
                 const float* __restrict__ krel, const float* __restrict__ vrel,
                 float* __restrict__ KR, float* __restrict__ VR, int nsrc, int H)
{
    extern __shared__ float sh[];
    float* skr = sh;
    float* svr = sh + H * 256;
    for (int i = threadIdx.x; i < H * 256; i += blockDim.x) {
        skr[i] = krel[i]; svr[i] = vrel[i];
    }
    __syncthreads();
    const int fout = H << 4;
    int tid = blockIdx.x * blockDim.x + threadIdx.x;
    if (tid >= nsrc * fout) return;
    int n = tid / fout, c = tid - n * fout;
    int h = c >> 4, eo = c & 15;
    const float4* kin = (const float4*)(KQV + (size_t)n * S + h * 16);
    const float4* vin = (const float4*)(KQV + (size_t)n * S + 2 * foutp + h * 16);
    const float* km = skr + h * 256 + eo;
    const float* vm = svr + h * 256 + eo;
    float ak = 0.f, av = 0.f;
#pragma unroll
    for (int j = 0; j < 4; j++) {
        float4 k4 = kin[j], v4 = vin[j];
        const float* kmj = km + (j << 6);
        const float* vmj = vm + (j << 6);
        ak += k4.x * kmj[0] + k4.y * kmj[16] + k4.z * kmj[32] + k4.w * kmj[48];
        av += v4.x * vmj[0] + v4.y * vmj[16] + v4.z * vmj[32] + v4.w * vmj[48];
    }
    KR[tid] = ak; VR[tid] = av;
}

// Merged score+exp+denominator pass (scores tiny; no max-shift needed).
__global__ __launch_bounds__(256)
void score_exp_kernel(const int* __restrict__ ep0, const int* __restrict__ ep1,
                      const int* __restrict__ flagp, const int* __restrict__ layp,
                      const float* __restrict__ Qb, int S,
                      const float* __restrict__ KR,
                      const float* __restrict__ prel, float* __restrict__ SC,
                      float* __restrict__ Db, int E, int H, int ns, int nd)
{
    const int* base = (*flagp) ? ep1 : ep0;
    const int lay = *layp;
    int tid = blockIdx.x * blockDim.x + threadIdx.x;
    if (tid >= E * H) return;
    int e = tid / H, h = tid - e * H;
    int s = min(max(edge_src(base, e, E, lay), 0), ns - 1);
    int d = min(max(edge_dst(base, e, E, lay), 0), nd - 1);
    const float4* q = (const float4*)(Qb + (size_t)d * S + h * 16);
    const float4* k = (const float4*)(KR + ((size_t)s * H + h) * 16);
    float sc = 0.f;
#pragma unroll
    for (int j = 0; j < 4; j++) {
        float4 qa = q[j], kb = k[j];
        sc += qa.x * kb.x + qa.y * kb.y + qa.z * kb.z + qa.w * kb.w;
    }
    sc *= prel[h] * 0.25f;
    float ex = __expf(sc);
    SC[tid] = ex;
    atomicAdd(Db + (size_t)d * H + h, ex);
}

// Unnormalized weighted aggregation; one thread per (edge, 4 channels).
// Warp-coherent: 16 consecutive lanes cover one dst row -> coalesced REDs.
__global__ __launch_bounds__(256)
void agg_kernel(const int* __restrict__ ep0, const int* __restrict__ ep1,
                const int* __restrict__ flagp, const int* __restrict__ layp,
                const float* __restrict__ VR, const float* __restrict__ SC,
                float* __restrict__ AG, int E, int H, int ns, int nd)
{
    const int* base = (*flagp) ? ep1 : ep0;
    const int lay = *layp;
    const int f4 = H * 4;
    int tid = blockIdx.x * blockDim.x + threadIdx.x;
    if (tid >= E * f4) return;
    int e = tid / f4, c4 = tid - e * f4;
    int h = c4 >> 2;
    int s = min(max(edge_src(base, e, E, lay), 0), ns - 1);
    int d = min(max(edge_dst(base, e, E, lay), 0), nd - 1);
    float ex = __ldg(SC + (size_t)e * H + h);
    float4 v = *(const float4*)(VR + ((size_t)s * f4 + c4) * 4);
    v.x *= ex; v.y *= ex; v.z *= ex; v.w *= ex;
    red_add_v4(AG + ((size_t)d * f4 + c4) * 4, v);
}

// ---------------- host orchestration ----------------

extern "C" void kernel_launch(void* const* d_in, const int* in_sizes, int n_in,
                              void* d_out, int out_size)
{
    static const long long ESIZE[30] = {
        25600000, 6400000, 320000,
        500000, 500000, 400000, 200000, 200000,
        32768, 128, 16384, 128, 8192, 128,
        147456, 1152, 10240, 10240, 40, 49152, 384, 3,
        73728, 576, 5120, 5120, 20, 12288, 192, 3
    };
    const void* P[30];
    bool got[30];
    for (int j = 0; j < 30; j++) { got[j] = false; P[j] = nullptr; }
    for (int i = 0; i < n_in; i++) {
        for (int j = 0; j < 30; j++) {
            if (!got[j] && (long long)in_sizes[i] == ESIZE[j]) {
                P[j] = d_in[i]; got[j] = true; break;
            }
        }
    }
    for (int j = 0; j < 30; j++) if (!got[j]) return;

    const float* x_in[3]  = {(const float*)P[0], (const float*)P[1], (const float*)P[2]};
    const int*   eptr[5]  = {(const int*)P[3], (const int*)P[4], (const int*)P[5],
                             (const int*)P[6], (const int*)P[7]};
    const float* lin_w[3] = {(const float*)P[8], (const float*)P[10], (const float*)P[12]};
    const float* lin_b[3] = {(const float*)P[9], (const float*)P[11], (const float*)P[13]};
    const float* kqv_w[2] = {(const float*)P[14], (const float*)P[22]};
    const float* kqv_b[2] = {(const float*)P[15], (const float*)P[23]};
    const float* krel[2]  = {(const float*)P[16], (const float*)P[24]};
    const float* vrel[2]  = {(const float*)P[17], (const float*)P[25]};
    const float* prel[2]  = {(const float*)P[18], (const float*)P[26]};
    const float* outw[2]  = {(const float*)P[19], (const float*)P[27]};
    const float* outb[2]  = {(const float*)P[20], (const float*)P[28]};
    const float* skipv[2] = {(const float*)P[21], (const float*)P[29]};

    float *X, *Y, *KQV, *KR, *VR, *SCb, *Db, *AG;
    int* FL;
#define GETSYM(p, s) do { if (cudaGetSymbolAddress((void**)&(p), s) != cudaSuccess) return; } while (0)
    GETSYM(X,  g_X);  GETSYM(Y,  g_Y);  GETSYM(KQV, g_KQV);
    GETSYM(KR, g_KR); GETSYM(VR, g_VR); GETSYM(SCb, g_SC);
    GETSYM(Db, g_DEN); GETSYM(AG, g_AGG); GETSYM(FL, g_flags);
#undef GETSYM

    const int ntyp[3]  = {NPAPER, NAUTH, NINST};
    const int roff[3]  = {0, NPAPER, NPAPER + NAUTH};
    const int idim[3]  = {256, 128, 64};
    // EDGE_TYPES = [(1,0), (0,0), (0,1), (1,2), (2,1)]
    const int esrc[5]  = {1, 0, 0, 1, 2};
    const int edst[5]  = {0, 0, 1, 2, 1};
    const int ecnt[5]  = {250000, 250000, 200000, 100000, 100000};
    const int kroff[5] = {0, 50000, 150000, 250000, 300000};
    const int scoff[5] = {0, 250000, 500000, 700000, 800000};
    const int* epri[5]  = {eptr[0], eptr[1], eptr[2], eptr[3], eptr[4]};
    const int* ealt[5]  = {eptr[1], eptr[0], eptr[2], eptr[4], eptr[3]};
    const int* eflag[5] = {FL + 0, FL + 0, FL + 0, FL + 1, FL + 1};
    int* LAY = FL + 2;

    resolve_kernel<<<1, 1024>>>(eptr[0], eptr[3], eptr[4]);

    const int MAXMB = (NPAPER + 127) / 128;   // 782

    // ---- input projections: X = relu(x @ lin_w + lin_b) ----
    {
        GB gb; gb.H = 1;
        for (int t = 0; t < 3; t++) {
            gb.A[t] = x_in[t];  gb.lda[t] = idim[t];
            gb.W[t] = lin_w[t]; gb.ldw[t] = 128;
            gb.Bias[t] = lin_b[t];
            gb.C[t] = X + (size_t)roff[t] * 128; gb.ldc[t] = 128;
            gb.R[t] = nullptr; gb.S[t] = nullptr; gb.D[t] = nullptr;
            gb.M[t] = ntyp[t]; gb.K[t] = idim[t];
        }
        gemm_tf32<<<dim3(2, MAXMB, 3), 256>>>(gb, 0, 1);
    }

    for (int li = 0; li < 2; li++) {
        const int H = li ? 4 : 8;
        const int fout = H * 16;
        const int S = 3 * fout;
        const float* Xin = li ? Y : X;

        // fused kqv projection, batched over types
        {
            GB gb; gb.H = 1;
            for (int t = 0; t < 3; t++) {
                gb.A[t] = Xin + (size_t)roff[t] * 128; gb.lda[t] = 128;
                gb.W[t] = kqv_w[li] + (size_t)t * 128 * S; gb.ldw[t] = S;
                gb.Bias[t] = kqv_b[li] + t * S;
                gb.C[t] = KQV + (size_t)roff[t] * S; gb.ldc[t] = S;
                gb.R[t] = nullptr; gb.S[t] = nullptr; gb.D[t] = nullptr;
                gb.M[t] = ntyp[t]; gb.K[t] = 128;
            }
            gemm_tf32<<<dim3(S / 64, MAXMB, 3), 256>>>(gb, 0, 0);
        }

        // init segment buffers (den + agg)
        {
            int nD4 = NTOT * H / 4, nA4 = NTOT * fout / 4;
            init_kernel<<<(nA4 + 255) / 256, 256>>>((float4*)Db, (float4*)AG, nD4, nA4);
        }

        // per-edge-type relation transforms over source nodes
        for (int e = 0; e < 5; e++) {
            int ns = ntyp[esrc[e]];
            int tot = ns * fout;
            size_t shb = (size_t)2 * H * 256 * sizeof(float);
            relx_kernel<<<(tot + 255) / 256, 256, shb>>>(
                KQV + (size_t)roff[esrc[e]] * S, S, fout,
                krel[li] + e * H * 256, vrel[li] + e * H * 256,
                KR + (size_t)kroff[e] * fout, VR + (size_t)kroff[e] * fout, ns, H);
        }

        // scores + exp + denominator
        for (int e = 0; e < 5; e++) {
            int tot = ecnt[e] * H;
            score_exp_kernel<<<(tot + 255) / 256, 256>>>(
                epri[e], ealt[e], eflag[e], LAY,
                KQV + (size_t)roff[edst[e]] * S + fout, S,
                KR + (size_t)kroff[e] * fout,
                prel[li] + e * H, SCb + (size_t)scoff[e] * H,
                Db + (size_t)roff[edst[e]] * H, ecnt[e], H,
                ntyp[esrc[e]], ntyp[edst[e]]);
        }
        // unnormalized weighted aggregation (normalize in GEMM)
        for (int e = 0; e < 5; e++) {
            int tot = ecnt[e] * (fout / 4);
            agg_kernel<<<(tot + 255) / 256, 256>>>(
                epri[e], ealt[e], eflag[e], LAY,
                VR + (size_t)kroff[e] * fout,
                SCb + (size_t)scoff[e] * H,
                AG + (size_t)roff[edst[e]] * fout, ecnt[e], H,
                ntyp[esrc[e]], ntyp[edst[e]]);
        }

        // output projection (batched; normalizes A by den inside the load)
        if (li == 0) {
            GB gb; gb.H = H;
            for (int t = 0; t < 3; t++) {
                gb.A[t] = AG + (size_t)roff[t] * 128; gb.lda[t] = 128;
                gb.W[t] = outw[0] + (size_t)t * 128 * 128; gb.ldw[t] = 128;
                gb.Bias[t] = outb[0] + t * 128;
                gb.C[t] = Y + (size_t)roff[t] * 128; gb.ldc[t] = 128;
                gb.R[t] = Xin + (size_t)roff[t] * 128; gb.S[t] = skipv[0] + t;
                gb.D[t] = Db + (size_t)roff[t] * H;
                gb.M[t] = ntyp[t]; gb.K[t] = 128;
            }
            gemm_tf32<<<dim3(2, MAXMB, 3), 256>>>(gb, 1, 0);
        } else {
            const size_t ooff[3] = {0, (size_t)NPAPER * 64, (size_t)(NPAPER + NAUTH) * 64};
            const long long need[3] = {6400000LL, 9600000LL, 9920000LL};
            GB gb; gb.H = H;
            for (int t = 0; t < 3; t++) {
                gb.A[t] = AG + (size_t)roff[t] * 64; gb.lda[t] = 64;
                gb.W[t] = outw[1] + (size_t)t * 64 * 64; gb.ldw[t] = 64;
                gb.Bias[t] = outb[1] + t * 64;
                gb.C[t] = (float*)d_out + ooff[t]; gb.ldc[t] = 64;
                gb.R[t] = nullptr; gb.S[t] = nullptr;
                gb.D[t] = Db + (size_t)roff[t] * H;
                gb.M[t] = ((long long)out_size >= need[t]) ? ntyp[t] : 0;
                gb.K[t] = 64;
            }
            gemm_tf32<<<dim3(1, MAXMB, 3), 256>>>(gb, 1, 0);
        }
    }
}

// round 12
// speedup vs baseline: 1.5525x; 1.0262x over previous
#include <cuda_runtime.h>
#include <cstdint>

#define NPAPER 100000
#define NAUTH  50000
#define NINST  5000
#define NTOT   155000
#define SRCROWS 305000
#define ETOT   900000

// ---------------- device scratch (no allocations allowed) ----------------
__device__ __align__(256) float g_X[(size_t)NTOT*128];
__device__ __align__(256) float g_Y[(size_t)NTOT*128];
__device__ __align__(256) float g_KQV[(size_t)NTOT*384];
__device__ __align__(256) float g_KR[(size_t)SRCROWS*128];
__device__ __align__(256) float g_VR[(size_t)SRCROWS*128];
__device__ __align__(256) float g_DEN[(size_t)NTOT*8];
__device__ __align__(256) float g_AGG[(size_t)NTOT*128];
__device__ int g_flags[3];

// ---------------- helpers ----------------

__device__ __forceinline__ float gelu_f(float x) {
    return 0.5f * x * (1.f + erff(x * 0.70710678118654752f));
}

__device__ __forceinline__ void split_tf32(float v, float& hi, float& lo) {
    uint32_t h, l;
    asm("cvt.rna.tf32.f32 %0, %1;" : "=r"(h) : "f"(v));
    float hf = __uint_as_float(h);
    asm("cvt.rna.tf32.f32 %0, %1;" : "=r"(l) : "f"(v - hf));
    hi = hf; lo = __uint_as_float(l);
}

__device__ __forceinline__ void mma_tf32(float c[4], const uint32_t a[4],
                                         uint32_t b0, uint32_t b1) {
    asm volatile(
        "mma.sync.aligned.m16n8k8.row.col.f32.tf32.tf32.f32 "
        "{%0,%1,%2,%3}, {%4,%5,%6,%7}, {%8,%9}, {%0,%1,%2,%3};"
        : "+f"(c[0]), "+f"(c[1]), "+f"(c[2]), "+f"(c[3])
        : "r"(a[0]), "r"(a[1]), "r"(a[2]), "r"(a[3]), "r"(b0), "r"(b1));
}

__device__ __forceinline__ void red_add_v4(float* p, float4 v) {
    asm volatile("red.global.add.v4.f32 [%0], {%1,%2,%3,%4};"
        :: "l"(p), "f"(v.x), "f"(v.y), "f"(v.z), "f"(v.w) : "memory");
}

__device__ __forceinline__ void red_add_f(float* p, float v) {
    asm volatile("red.global.add.f32 [%0], %1;" :: "l"(p), "f"(v) : "memory");
}

__device__ __forceinline__ int edge_src(const int* b, int e, int E, int lay) {
    return lay ? b[2 * e] : b[e];
}
__device__ __forceinline__ int edge_dst(const int* b, int e, int E, int lay) {
    return lay ? b[2 * e + 1] : b[E + e];
}

struct GB {  // per-node-type batched GEMM descriptors (z-indexed)
    const float* A[3];
    const float* W[3];
    const float* Bias[3];
    float*       C[3];
    const float* R[3];
    const float* S[3];
    const float* D[3];   // per-row/head denominators (A pre-divide), or null
    int M[3], K[3], lda[3], ldw[3], ldc[3];
    int H;               // heads for D indexing
};

// ---------------- kernels ----------------

__global__ void resolve_kernel(const int* __restrict__ t01,
                               const int* __restrict__ t34a,
                               const int* __restrict__ t34b)
{
    __shared__ int s[8];
    if (threadIdx.x < 8) s[threadIdx.x] = 0;
    __syncthreads();
    int ah1 = 0, ah2 = 0, aodd = 0, bh1 = 0, bh2 = 0, bodd = 0, ch1 = 0, cev = 0;
    for (int i = threadIdx.x; i < 200000; i += blockDim.x) {
        int va = t34a[i], vb = t34b[i];
        if (i < 100000) { ah1 = max(ah1, va); bh1 = max(bh1, vb); }
        else            { ah2 = max(ah2, va); bh2 = max(bh2, vb); }
        if (i & 1) { aodd = max(aodd, va); bodd = max(bodd, vb); }
    }
    for (int i = threadIdx.x; i < 500000; i += blockDim.x) {
        int vc = t01[i];
        if (i < 250000) ch1 = max(ch1, vc);
        if (!(i & 1))   cev = max(cev, vc);
    }
    atomicMax(&s[0], ah1); atomicMax(&s[1], ah2); atomicMax(&s[2], aodd);
    atomicMax(&s[3], bh1); atomicMax(&s[4], bh2); atomicMax(&s[5], bodd);
    atomicMax(&s[6], ch1); atomicMax(&s[7], cev);
    __syncthreads();
    if (threadIdx.x == 0) {
        int m4 = min(min(s[0], s[1]), min(s[3], s[4]));
        int layE2 = (m4 >= 10000) ? 1 : 0;
        g_flags[2] = layE2;
        g_flags[1] = layE2 ? ((s[2] >= 10000) ? 1 : 0)
                           : ((s[1] >= 10000) ? 1 : 0);
        int srcmax = layE2 ? s[7] : s[6];
        g_flags[0] = (srcmax >= 60000) ? 1 : 0;
    }
}

__global__ void init_kernel(float4* __restrict__ D, float4* __restrict__ A,
                            int nD4, int nA4) {
    int i = blockIdx.x * blockDim.x + threadIdx.x;
    float4 z = make_float4(0.f, 0.f, 0.f, 0.f);
    if (i < nD4) D[i] = z;
    if (i < nA4) A[i] = z;
}

// Batched (z = node type) C = epilogue(actA(A) @ W + bias) via 3xTF32 MMA.
// Block tile 128x64x32 with register-prefetch pipeline. K % 32 == 0.
// If D[z] != null, A element (m, k) is pre-divided by D[m*H + k/16].
__global__ __launch_bounds__(256)
void gemm_tf32(GB gb, int geluA, int reluO)
{
    const int z = blockIdx.z;
    const int M = gb.M[z];
    const int m0 = blockIdx.y * 128;
    if (m0 >= M) return;
    const int K = gb.K[z], lda = gb.lda[z], ldw = gb.ldw[z], ldc = gb.ldc[z];
    const float* __restrict__ A = gb.A[z];
    const float* __restrict__ W = gb.W[z];
    const float* __restrict__ bias = gb.Bias[z];
    const float* __restrict__ resid = gb.R[z];
    const float* __restrict__ Dn = gb.D[z];
    const int H = gb.H;
    float* __restrict__ C = gb.C[z];

    __shared__ float Ah[32][129], Al[32][129];   // [k][m]
    __shared__ float Bh[64][33],  Bl[64][33];    // [n][k]
    const int tid = threadIdx.x;
    const int lane = tid & 31, wid = tid >> 5;
    const int n0 = blockIdx.x * 64;
    const int moff = (wid & 3) * 32, noff = (wid >> 2) * 32;
    const int am = tid & 127, ak = (tid >> 7) * 16;
    const int bk = tid & 31,  bn = (tid >> 5) * 8;
    const bool arow_ok = (m0 + am < M);

    float c[2][4][4];
#pragma unroll
    for (int mt = 0; mt < 2; mt++)
#pragma unroll
        for (int nt = 0; nt < 4; nt++)
#pragma unroll
            for (int i = 0; i < 4; i++) c[mt][nt][i] = 0.f;

    float4 ra[4], rb[2];
    const float4 fz = make_float4(0.f, 0.f, 0.f, 0.f);

#define LDG_TILE(K0)                                                          \
    do {                                                                      \
        const float* ap = A + (size_t)(m0 + am) * lda + (K0) + ak;            \
        if (arow_ok) {                                                        \
            ra[0] = *(const float4*)(ap);      ra[1] = *(const float4*)(ap + 4); \
            ra[2] = *(const float4*)(ap + 8);  ra[3] = *(const float4*)(ap + 12);\
        } else { ra[0] = fz; ra[1] = fz; ra[2] = fz; ra[3] = fz; }             \
        if (Dn && arow_ok) {                                                  \
            float dn = __ldg(Dn + (size_t)(m0 + am) * H + (((K0) + ak) >> 4)); \
            float inv = 1.f / fmaxf(dn, 1e-16f);                              \
            _Pragma("unroll")                                                 \
            for (int j = 0; j < 4; j++) {                                     \
                ra[j].x *= inv; ra[j].y *= inv; ra[j].z *= inv; ra[j].w *= inv; \
            }                                                                 \
        }                                                                     \
        if (geluA) {                                                          \
            _Pragma("unroll")                                                 \
            for (int j = 0; j < 4; j++) {                                     \
                ra[j].x = gelu_f(ra[j].x); ra[j].y = gelu_f(ra[j].y);         \
                ra[j].z = gelu_f(ra[j].z); ra[j].w = gelu_f(ra[j].w);         \
            }                                                                 \
        }                                                                     \
        const float* bp = W + (size_t)((K0) + bk) * ldw + n0 + bn;            \
        rb[0] = *(const float4*)(bp); rb[1] = *(const float4*)(bp + 4);       \
    } while (0)

    LDG_TILE(0);
    const int niter = K >> 5;
    for (int it = 0; it < niter; it++) {
        __syncthreads();
#pragma unroll
        for (int j = 0; j < 4; j++) {
            float h, l;
            split_tf32(ra[j].x, h, l); Ah[ak + j*4 + 0][am] = h; Al[ak + j*4 + 0][am] = l;
            split_tf32(ra[j].y, h, l); Ah[ak + j*4 + 1][am] = h; Al[ak + j*4 + 1][am] = l;
            split_tf32(ra[j].z, h, l); Ah[ak + j*4 + 2][am] = h; Al[ak + j*4 + 2][am] = l;
            split_tf32(ra[j].w, h, l); Ah[ak + j*4 + 3][am] = h; Al[ak + j*4 + 3][am] = l;
        }
#pragma unroll
        for (int j = 0; j < 2; j++) {
            float h, l;
            split_tf32(rb[j].x, h, l); Bh[bn + j*4 + 0][bk] = h; Bl[bn + j*4 + 0][bk] = l;
            split_tf32(rb[j].y, h, l); Bh[bn + j*4 + 1][bk] = h; Bl[bn + j*4 + 1][bk] = l;
            split_tf32(rb[j].z, h, l); Bh[bn + j*4 + 2][bk] = h; Bl[bn + j*4 + 2][bk] = l;
            split_tf32(rb[j].w, h, l); Bh[bn + j*4 + 3][bk] = h; Bl[bn + j*4 + 3][bk] = l;
        }
        __syncthreads();
        if (it + 1 < niter) LDG_TILE((it + 1) << 5);
#pragma unroll
        for (int ks = 0; ks < 32; ks += 8) {
            const int kk = ks + (lane & 3);
            uint32_t ah[2][4], al[2][4];
#pragma unroll
            for (int mt = 0; mt < 2; mt++) {
                int r = moff + mt * 16 + (lane >> 2);
                ah[mt][0] = __float_as_uint(Ah[kk][r]);
                ah[mt][1] = __float_as_uint(Ah[kk][r + 8]);
                ah[mt][2] = __float_as_uint(Ah[kk + 4][r]);
                ah[mt][3] = __float_as_uint(Ah[kk + 4][r + 8]);
                al[mt][0] = __float_as_uint(Al[kk][r]);
                al[mt][1] = __float_as_uint(Al[kk][r + 8]);
                al[mt][2] = __float_as_uint(Al[kk + 4][r]);
                al[mt][3] = __float_as_uint(Al[kk + 4][r + 8]);
            }
#pragma unroll
            for (int nt = 0; nt < 4; nt++) {
                int bc = noff + nt * 8 + (lane >> 2);
                uint32_t bh0 = __float_as_uint(Bh[bc][kk]);
                uint32_t bh1 = __float_as_uint(Bh[bc][kk + 4]);
                uint32_t bl0 = __float_as_uint(Bl[bc][kk]);
                uint32_t bl1 = __float_as_uint(Bl[bc][kk + 4]);
#pragma unroll
                for (int mt = 0; mt < 2; mt++) {
                    mma_tf32(c[mt][nt], al[mt], bh0, bh1);
                    mma_tf32(c[mt][nt], ah[mt], bl0, bl1);
                    mma_tf32(c[mt][nt], ah[mt], bh0, bh1);
                }
            }
        }
    }
#undef LDG_TILE

    float sa = 0.f;
    if (resid) { float s = *gb.S[z]; sa = 1.f / (1.f + __expf(-s)); }
#pragma unroll
    for (int mt = 0; mt < 2; mt++) {
#pragma unroll
        for (int half = 0; half < 2; half++) {
            int cm = m0 + moff + mt * 16 + (lane >> 2) + half * 8;
            if (cm >= M) continue;
#pragma unroll
            for (int nt = 0; nt < 4; nt++) {
                int cn = n0 + noff + nt * 8 + (lane & 3) * 2;
                float v0 = c[mt][nt][half * 2 + 0] + bias[cn];
                float v1 = c[mt][nt][half * 2 + 1] + bias[cn + 1];
                if (reluO) { v0 = fmaxf(v0, 0.f); v1 = fmaxf(v1, 0.f); }
                if (resid) {
                    float2 r2 = *(const float2*)(resid + (size_t)cm * ldc + cn);
                    v0 = sa * v0 + (1.f - sa) * r2.x;
                    v1 = sa * v1 + (1.f - sa) * r2.y;
                }
                *(float2*)(C + (size_t)cm * ldc + cn) = make_float2(v0, v1);
            }
        }
    }
}

// Per-edge-type relation transform over source nodes, reading fused KQV.
__global__ __launch_bounds__(256)
void relx_kernel(const float* __restrict__ KQV, int S, int foutp,
                 const float* __restrict__ krel, const float* __restrict__ vrel,
                 float* __restrict__ KR, float* __restrict__ VR, int nsrc, int H)
{
    extern __shared__ float sh[];
    float* skr = sh;
    float* svr = sh + H * 256;
    for (int i = threadIdx.x; i < H * 256; i += blockDim.x) {
        skr[i] = krel[i]; svr[i] = vrel[i];
    }
    __syncthreads();
    const int fout = H << 4;
    int tid = blockIdx.x * blockDim.x + threadIdx.x;
    if (tid >= nsrc * fout) return;
    int n = tid / fout, c = tid - n * fout;
    int h = c >> 4, eo = c & 15;
    const float4* kin = (const float4*)(KQV + (size_t)n * S + h * 16);
    const float4* vin = (const float4*)(KQV + (size_t)n * S + 2 * foutp + h * 16);
    const float* km = skr + h * 256 + eo;
    const float* vm = svr + h * 256 + eo;
    float ak = 0.f, av = 0.f;
#pragma unroll
    for (int j = 0; j < 4; j++) {
        float4 k4 = kin[j], v4 = vin[j];
        const float* kmj = km + (j << 6);
        const float* vmj = vm + (j << 6);
        ak += k4.x * kmj[0] + k4.y * kmj[16] + k4.z * kmj[32] + k4.w * kmj[48];
        av += v4.x * vmj[0] + v4.y * vmj[16] + v4.z * vmj[32] + v4.w * vmj[48];
    }
    KR[tid] = ak; VR[tid] = av;
}

// FUSED edge kernel with agg-style coalesced mapping:
// one thread per (edge, 4 channels). Each 4-lane group covers one head:
// partial q.k dot -> shfl reduce -> ex -> RED den (lane j==0) + RED ex*v.
// Same RED coalescing as the proven agg kernel; score pass absorbed.
__global__ __launch_bounds__(256)
void edge_fused_kernel(const int* __restrict__ ep0, const int* __restrict__ ep1,
                       const int* __restrict__ flagp, const int* __restrict__ layp,
                       const float* __restrict__ Qb, int S,
                       const float* __restrict__ KR, const float* __restrict__ VR,
                       const float* __restrict__ prel,
                       float* __restrict__ Db, float* __restrict__ AG,
                       int E, int H, int ns, int nd)
{
    const int* base = (*flagp) ? ep1 : ep0;
    const int lay = *layp;
    const int f4 = H * 4;
    int tid = blockIdx.x * blockDim.x + threadIdx.x;
    if (tid >= E * f4) return;   // E*f4 % 32 == 0: whole warps exit, shfl safe
    int e = tid / f4, c4 = tid - e * f4;
    int h = c4 >> 2, j = c4 & 3;
    int s = min(max(edge_src(base, e, E, lay), 0), ns - 1);
    int d = min(max(edge_dst(base, e, E, lay), 0), nd - 1);
    // cooperative score: each lane handles 4 dims of its head
    float4 q4 = *(const float4*)(Qb + (size_t)d * S + h * 16 + j * 4);
    float4 k4 = *(const float4*)(KR + ((size_t)s * H + h) * 16 + j * 4);
    float p = q4.x * k4.x + q4.y * k4.y + q4.z * k4.z + q4.w * k4.w;
    p += __shfl_xor_sync(0xffffffffu, p, 1);
    p += __shfl_xor_sync(0xffffffffu, p, 2);
    float ex = __expf(p * __ldg(prel + h) * 0.25f);
    if (j == 0) red_add_f(Db + (size_t)d * H + h, ex);
    float4 v = *(const float4*)(VR + ((size_t)s * f4 + c4) * 4);
    v.x *= ex; v.y *= ex; v.z *= ex; v.w *= ex;
    red_add_v4(AG + ((size_t)d * f4 + c4) * 4, v);
}

// ---------------- host orchestration ----------------

extern "C" void kernel_launch(void* const* d_in, const int* in_sizes, int n_in,
                              void* d_out, int out_size)
{
    static const long long ESIZE[30] = {
        25600000, 6400000, 320000,
        500000, 500000, 400000, 200000, 200000,
        32768, 128, 16384, 128, 8192, 128,
        147456, 1152, 10240, 10240, 40, 49152, 384, 3,
        73728, 576, 5120, 5120, 20, 12288, 192, 3
    };
    const void* P[30];
    bool got[30];
    for (int j = 0; j < 30; j++) { got[j] = false; P[j] = nullptr; }
    for (int i = 0; i < n_in; i++) {
        for (int j = 0; j < 30; j++) {
            if (!got[j] && (long long)in_sizes[i] == ESIZE[j]) {
                P[j] = d_in[i]; got[j] = true; break;
            }
        }
    }
    for (int j = 0; j < 30; j++) if (!got[j]) return;

    const float* x_in[3]  = {(const float*)P[0], (const float*)P[1], (const float*)P[2]};
    const int*   eptr[5]  = {(const int*)P[3], (const int*)P[4], (const int*)P[5],
                             (const int*)P[6], (const int*)P[7]};
    const float* lin_w[3] = {(const float*)P[8], (const float*)P[10], (const float*)P[12]};
    const float* lin_b[3] = {(const float*)P[9], (const float*)P[11], (const float*)P[13]};
    const float* kqv_w[2] = {(const float*)P[14], (const float*)P[22]};
    const float* kqv_b[2] = {(const float*)P[15], (const float*)P[23]};
    const float* krel[2]  = {(const float*)P[16], (const float*)P[24]};
    const float* vrel[2]  = {(const float*)P[17], (const float*)P[25]};
    const float* prel[2]  = {(const float*)P[18], (const float*)P[26]};
    const float* outw[2]  = {(const float*)P[19], (const float*)P[27]};
    const float* outb[2]  = {(const float*)P[20], (const float*)P[28]};
    const float* skipv[2] = {(const float*)P[21], (const float*)P[29]};

    float *X, *Y, *KQV, *KR, *VR, *Db, *AG;
    int* FL;
#define GETSYM(p, s) do { if (cudaGetSymbolAddress((void**)&(p), s) != cudaSuccess) return; } while (0)
    GETSYM(X,  g_X);  GETSYM(Y,  g_Y);  GETSYM(KQV, g_KQV);
    GETSYM(KR, g_KR); GETSYM(VR, g_VR);
    GETSYM(Db, g_DEN); GETSYM(AG, g_AGG); GETSYM(FL, g_flags);
#undef GETSYM

    const int ntyp[3]  = {NPAPER, NAUTH, NINST};
    const int roff[3]  = {0, NPAPER, NPAPER + NAUTH};
    const int idim[3]  = {256, 128, 64};
    // EDGE_TYPES = [(1,0), (0,0), (0,1), (1,2), (2,1)]
    const int esrc[5]  = {1, 0, 0, 1, 2};
    const int edst[5]  = {0, 0, 1, 2, 1};
    const int ecnt[5]  = {250000, 250000, 200000, 100000, 100000};
    const int kroff[5] = {0, 50000, 150000, 250000, 300000};
    const int* epri[5]  = {eptr[0], eptr[1], eptr[2], eptr[3], eptr[4]};
    const int* ealt[5]  = {eptr[1], eptr[0], eptr[2], eptr[4], eptr[3]};
    const int* eflag[5] = {FL + 0, FL + 0, FL + 0, FL + 1, FL + 1};
    int* LAY = FL + 2;

    resolve_kernel<<<1, 1024>>>(eptr[0], eptr[3], eptr[4]);

    const int MAXMB = (NPAPER + 127) / 128;   // 782

    // ---- input projections: X = relu(x @ lin_w + lin_b) ----
    {
        GB gb; gb.H = 1;
        for (int t = 0; t < 3; t++) {
            gb.A[t] = x_in[t];  gb.lda[t] = idim[t];
            gb.W[t] = lin_w[t]; gb.ldw[t] = 128;
            gb.Bias[t] = lin_b[t];
            gb.C[t] = X + (size_t)roff[t] * 128; gb.ldc[t] = 128;
            gb.R[t] = nullptr; gb.S[t] = nullptr; gb.D[t] = nullptr;
            gb.M[t] = ntyp[t]; gb.K[t] = idim[t];
        }
        gemm_tf32<<<dim3(2, MAXMB, 3), 256>>>(gb, 0, 1);
    }

    for (int li = 0; li < 2; li++) {
        const int H = li ? 4 : 8;
        const int fout = H * 16;
        const int S = 3 * fout;
        const float* Xin = li ? Y : X;

        // fused kqv projection, batched over types
        {
            GB gb; gb.H = 1;
            for (int t = 0; t < 3; t++) {
                gb.A[t] = Xin + (size_t)roff[t] * 128; gb.lda[t] = 128;
                gb.W[t] = kqv_w[li] + (size_t)t * 128 * S; gb.ldw[t] = S;
                gb.Bias[t] = kqv_b[li] + t * S;
                gb.C[t] = KQV + (size_t)roff[t] * S; gb.ldc[t] = S;
                gb.R[t] = nullptr; gb.S[t] = nullptr; gb.D[t] = nullptr;
                gb.M[t] = ntyp[t]; gb.K[t] = 128;
            }
            gemm_tf32<<<dim3(S / 64, MAXMB, 3), 256>>>(gb, 0, 0);
        }

        // init segment buffers (den + agg)
        {
            int nD4 = NTOT * H / 4, nA4 = NTOT * fout / 4;
            init_kernel<<<(nA4 + 255) / 256, 256>>>((float4*)Db, (float4*)AG, nD4, nA4);
        }

        // per-edge-type relation transforms over source nodes
        for (int e = 0; e < 5; e++) {
            int ns = ntyp[esrc[e]];
            int tot = ns * fout;
            size_t shb = (size_t)2 * H * 256 * sizeof(float);
            relx_kernel<<<(tot + 255) / 256, 256, shb>>>(
                KQV + (size_t)roff[esrc[e]] * S, S, fout,
                krel[li] + e * H * 256, vrel[li] + e * H * 256,
                KR + (size_t)kroff[e] * fout, VR + (size_t)kroff[e] * fout, ns, H);
        }

        // FUSED edge phase: cooperative score + exp + den + aggregation
        for (int e = 0; e < 5; e++) {
            int tot = ecnt[e] * (fout / 4);
            edge_fused_kernel<<<(tot + 255) / 256, 256>>>(
                epri[e], ealt[e], eflag[e], LAY,
                KQV + (size_t)roff[edst[e]] * S + fout, S,
                KR + (size_t)kroff[e] * fout, VR + (size_t)kroff[e] * fout,
                prel[li] + e * H,
                Db + (size_t)roff[edst[e]] * H,
                AG + (size_t)roff[edst[e]] * fout,
                ecnt[e], H, ntyp[esrc[e]], ntyp[edst[e]]);
        }

        // output projection (batched; normalizes A by den inside the load)
        if (li == 0) {
            GB gb; gb.H = H;
            for (int t = 0; t < 3; t++) {
                gb.A[t] = AG + (size_t)roff[t] * 128; gb.lda[t] = 128;
                gb.W[t] = outw[0] + (size_t)t * 128 * 128; gb.ldw[t] = 128;
                gb.Bias[t] = outb[0] + t * 128;
                gb.C[t] = Y + (size_t)roff[t] * 128; gb.ldc[t] = 128;
                gb.R[t] = Xin + (size_t)roff[t] * 128; gb.S[t] = skipv[0] + t;
                gb.D[t] = Db + (size_t)roff[t] * H;
                gb.M[t] = ntyp[t]; gb.K[t] = 128;
            }
            gemm_tf32<<<dim3(2, MAXMB, 3), 256>>>(gb, 1, 0);
        } else {
            const size_t ooff[3] = {0, (size_t)NPAPER * 64, (size_t)(NPAPER + NAUTH) * 64};
            const long long need[3] = {6400000LL, 9600000LL, 9920000LL};
            GB gb; gb.H = H;
            for (int t = 0; t < 3; t++) {
                gb.A[t] = AG + (size_t)roff[t] * 64; gb.lda[t] = 64;
                gb.W[t] = outw[1] + (size_t)t * 64 * 64; gb.ldw[t] = 64;
                gb.Bias[t] = outb[1] + t * 64;
                gb.C[t] = (float*)d_out + ooff[t]; gb.ldc[t] = 64;
                gb.R[t] = nullptr; gb.S[t] = nullptr;
                gb.D[t] = Db + (size_t)roff[t] * H;
                gb.M[t] = ((long long)out_size >= need[t]) ? ntyp[t] : 0;
                gb.K[t] = 64;
            }
            gemm_tf32<<<dim3(1, MAXMB, 3), 256>>>(gb, 1, 0);
        }
    }
}